// round 11
// baseline (speedup 1.0000x reference)
#include <cuda_runtime.h>
#include <math_constants.h>

#define NB 8
#define NPTS 4096
#define KNN 16
#define MPTS (NB * NPTS)
#define CH 32
#define NCLS 40
#define GR 32
#define G3 (GR * GR * GR)
#define GMIN (-5.5f)
#define CW (11.0f / 32.0f)
#define INVCW (32.0f / 11.0f)

__device__ int    g_cnt[NB * G3];     // zeroed by scan_kernel after use
__device__ int    g_start[NB * G3];   // per-batch exclusive offsets
__device__ int    g_cur[NB * G3];
__device__ int    g_pcell[MPTS];
__device__ float4 g_spt[MPTS];        // grid-ordered points (x,y,z,|p|^2)
__device__ int    g_soi[MPTS];        // slot -> original global index
__device__ int    g_knn[MPTS * KNN];
__device__ float  g_y[MPTS * CH];
__device__ float4 g_feat[MPTS * 17];
__device__ float  g_pool[NB * CH];

__device__ __forceinline__ int cellco(float v) {
    int c = (int)floorf((v - GMIN) * INVCW);
    return min(GR - 1, max(0, c));
}

__device__ __forceinline__ float safe_norm3(float x, float y, float z) {
    float s = x * x + y * y + z * z;
    return s > 0.f ? sqrtf(s) : 0.f;
}

__device__ __forceinline__ float angle3(float ax, float ay, float az,
                                        float bx, float by, float bz) {
    float cx = ay * bz - az * by;
    float cy = az * bx - ax * bz;
    float cz = ax * by - ay * bx;
    float cn = safe_norm3(cx, cy, cz);
    float d  = ax * bx + ay * by + az * bz;
    bool ok = (cn > 0.f) || (d != 0.f);
    return ok ? atan2f(cn, d) : 0.f;
}

// ---------------------------------------------------------------------------
// grid build (g_cnt starts zero: device-init + scan_kernel re-zeroes)
// ---------------------------------------------------------------------------
__global__ __launch_bounds__(256) void count_kernel(const float* __restrict__ pos) {
    int i = blockIdx.x * 256 + threadIdx.x;
    if (blockIdx.x == 0 && threadIdx.x < NB * CH) g_pool[threadIdx.x] = 0.f;
    int b = i >> 12;
    int cx = cellco(pos[3 * i + 0]);
    int cy = cellco(pos[3 * i + 1]);
    int cz = cellco(pos[3 * i + 2]);
    int cid = ((b * GR + cz) * GR + cy) * GR + cx;
    g_pcell[i] = cid;
    atomicAdd(&g_cnt[cid], 1);
}

__global__ __launch_bounds__(1024) void scan_kernel() {
    __shared__ int buf[1024];
    int b = blockIdx.x, t = threadIdx.x;
    int run = 0;
    for (int c = 0; c < G3 / 1024; c++) {
        int idx = b * G3 + c * 1024 + t;
        int v = g_cnt[idx];
        g_cnt[idx] = 0;                    // ready for next launch/replay
        buf[t] = v;
        __syncthreads();
        for (int off = 1; off < 1024; off <<= 1) {
            int x = buf[t];
            if (t >= off) x += buf[t - off];
            __syncthreads();
            buf[t] = x;
            __syncthreads();
        }
        int excl = buf[t] - v;
        g_start[idx] = run + excl;
        g_cur[idx]   = run + excl;
        run += buf[1023];
        __syncthreads();
    }
}

__global__ __launch_bounds__(256) void scatter_kernel(const float* __restrict__ pos) {
    int i = blockIdx.x * 256 + threadIdx.x;
    int b = i >> 12;
    int cid = g_pcell[i];
    int slot = atomicAdd(&g_cur[cid], 1);
    float x = pos[3 * i + 0], y = pos[3 * i + 1], z = pos[3 * i + 2];
    g_spt[b * NPTS + slot] = make_float4(x, y, z, x * x + y * y + z * z);
    g_soi[b * NPTS + slot] = i;
}

// scan one contiguous slot range [lo, lo+n) with the proven ballot machinery
__device__ __forceinline__ void scan_seg(
    int boff, int lo, int n, int q,
    float m2x, float m2y, float m2z,
    float& L, int& LI, float& tp, int lane)
{
    const unsigned FULL = 0xFFFFFFFFu;
    for (int off = 0; off < n; off += 32) {
        int k = off + lane;
        float d = CUDART_INF_F;
        int   oi = -1;
        if (k < n) {
            float4 c = g_spt[boff + lo + k];
            oi = g_soi[boff + lo + k];
            d = fmaf(c.x, m2x, fmaf(c.y, m2y, fmaf(c.z, m2z, c.w)));
            if (oi == q) d = CUDART_INF_F;
        }
        unsigned bal = __ballot_sync(FULL, d < tp);
        while (bal) {
            int src = __ffs(bal) - 1;
            float v = __shfl_sync(FULL, d, src);
            int  vi = __shfl_sync(FULL, oi, src);
            unsigned ble = __ballot_sync(FULL, L <= v);
            int pos_ = __popc(ble & 0xFFFFu);
            float Lup = __shfl_up_sync(FULL, L, 1);
            int  LIup = __shfl_up_sync(FULL, LI, 1);
            if (lane < 16) {
                if (lane == pos_)      { L = v;   LI = vi;   }
                else if (lane > pos_)  { L = Lup; LI = LIup; }
            }
            tp = __shfl_sync(FULL, L, 15);
            bal &= bal - 1;
        }
    }
}

// ---------------------------------------------------------------------------
// kNN v7: grid search over contiguous x-rows. One warp per query. Level-r
// cube scanned as rows (ring rows full-width; interior rows only their two
// new end cells). Terminate when 16th-best real d2 <= (box margin)^2.
// ---------------------------------------------------------------------------
__global__ __launch_bounds__(256) void knn_kernel(const float* __restrict__ pos) {
    const unsigned FULL = 0xFFFFFFFFu;
    const float INF = CUDART_INF_F;
    int lane = threadIdx.x & 31;
    int warp = threadIdx.x >> 5;
    int q     = blockIdx.x * 8 + warp;
    int batch = q >> 12;
    int boff  = batch * NPTS;

    float qx = pos[3 * q + 0], qy = pos[3 * q + 1], qz = pos[3 * q + 2];
    float m2x = -2.f * qx, m2y = -2.f * qy, m2z = -2.f * qz;
    float qw = qx * qx + qy * qy + qz * qz;
    int cx = cellco(qx), cy = cellco(qy), cz = cellco(qz);

    float L  = INF;
    int   LI = boff;
    float tp = INF;

    for (int r = 1; r < GR; r++) {
        if (r == 1) {
            // prefetch the 9 row extents in parallel (lanes 0..8)
            int lo9 = 0, n9 = 0;
            if (lane < 9) {
                int dz = lane / 3 - 1, dy = lane % 3 - 1;
                int az = cz + dz, ay = cy + dy;
                if (az >= 0 && az < GR && ay >= 0 && ay < GR) {
                    int xlo = max(0, cx - 1), xhi = min(GR - 1, cx + 1);
                    int cidlo = ((batch * GR + az) * GR + ay) * GR + xlo;
                    int cidhi = cidlo + (xhi - xlo);
                    lo9 = g_start[cidlo];
                    int end = ((cidhi & (G3 - 1)) == G3 - 1) ? NPTS
                                                             : g_start[cidhi + 1];
                    n9 = end - lo9;
                }
            }
#pragma unroll
            for (int row = 0; row < 9; row++) {
                int lo = __shfl_sync(FULL, lo9, row);
                int n  = __shfl_sync(FULL, n9, row);
                if (n > 0) scan_seg(boff, lo, n, q, m2x, m2y, m2z, L, LI, tp, lane);
            }
        } else {
            for (int dz = -r; dz <= r; dz++) {
                int az = cz + dz;
                if (az < 0 || az >= GR) continue;
                for (int dy = -r; dy <= r; dy++) {
                    int ay = cy + dy;
                    if (ay < 0 || ay >= GR) continue;
                    int rowbase = ((batch * GR + az) * GR + ay) * GR;
                    if (abs(dz) == r || abs(dy) == r) {
                        int xlo = max(0, cx - r), xhi = min(GR - 1, cx + r);
                        int cidlo = rowbase + xlo, cidhi = rowbase + xhi;
                        int lo = g_start[cidlo];
                        int end = ((cidhi & (G3 - 1)) == G3 - 1) ? NPTS
                                                                 : g_start[cidhi + 1];
                        if (end > lo) scan_seg(boff, lo, end - lo, q,
                                               m2x, m2y, m2z, L, LI, tp, lane);
                    } else {
                        if (cx - r >= 0) {
                            int cid = rowbase + cx - r;
                            int lo = g_start[cid];
                            int end = ((cid & (G3 - 1)) == G3 - 1) ? NPTS
                                                                   : g_start[cid + 1];
                            if (end > lo) scan_seg(boff, lo, end - lo, q,
                                                   m2x, m2y, m2z, L, LI, tp, lane);
                        }
                        if (cx + r < GR) {
                            int cid = rowbase + cx + r;
                            int lo = g_start[cid];
                            int end = ((cid & (G3 - 1)) == G3 - 1) ? NPTS
                                                                   : g_start[cid + 1];
                            if (end > lo) scan_seg(boff, lo, end - lo, q,
                                                   m2x, m2y, m2z, L, LI, tp, lane);
                        }
                    }
                }
            }
        }
        // exact termination: margin from q to the scanned box's faces
        float m = INF;
        if (cx - r > 0)      m = fminf(m, qx - (GMIN + (float)(cx - r) * CW));
        if (cx + r < GR - 1) m = fminf(m, (GMIN + (float)(cx + r + 1) * CW) - qx);
        if (cy - r > 0)      m = fminf(m, qy - (GMIN + (float)(cy - r) * CW));
        if (cy + r < GR - 1) m = fminf(m, (GMIN + (float)(cy + r + 1) * CW) - qy);
        if (cz - r > 0)      m = fminf(m, qz - (GMIN + (float)(cz - r) * CW));
        if (cz + r < GR - 1) m = fminf(m, (GMIN + (float)(cz + r + 1) * CW) - qz);
        if (tp + qw <= m * m * 0.999f) break;
    }

    if (lane < 16) g_knn[q * KNN + lane] = LI;
}

// ---------------------------------------------------------------------------
// conv1 (+ fused y; materializes PPF feats)
// ---------------------------------------------------------------------------
__global__ __launch_bounds__(256) void conv1_kernel(
    const float* __restrict__ pos, const float* __restrict__ nrm,
    const float* __restrict__ w1a, const float* __restrict__ b1a,
    const float* __restrict__ w1b, const float* __restrict__ b1b,
    const float* __restrict__ w2a, const float* __restrict__ b2a)
{
    __shared__ float4 sf[8][20];
    __shared__ float  sh[8][17][32];
    int warp = threadIdx.x >> 5;
    int lane = threadIdx.x & 31;
    int i    = blockIdx.x * 8 + warp;

    float wa0 = w1a[0 * 32 + lane], wa1 = w1a[1 * 32 + lane];
    float wa2 = w1a[2 * 32 + lane], wa3 = w1a[3 * 32 + lane];
    float ba  = b1a[lane];
    float wb[32];
#pragma unroll
    for (int k = 0; k < 32; k++) wb[k] = w1b[k * 32 + lane];
    float bb = b1b[lane];

    float pix = pos[3 * i + 0], piy = pos[3 * i + 1], piz = pos[3 * i + 2];
    float nix = nrm[3 * i + 0], niy = nrm[3 * i + 1], niz = nrm[3 * i + 2];

    int j = (lane < KNN) ? g_knn[i * KNN + lane] : i;
    float pjx = pos[3 * j + 0], pjy = pos[3 * j + 1], pjz = pos[3 * j + 2];
    float njx = nrm[3 * j + 0], njy = nrm[3 * j + 1], njz = nrm[3 * j + 2];

    float px = pjx - pix, py = pjy - piy, pz = pjz - piz;
    float f0 = safe_norm3(px, py, pz);
    float f1 = angle3(nix, niy, niz, px, py, pz);
    float f2 = angle3(njx, njy, njz, px, py, pz);
    float f3 = angle3(nix, niy, niz, njx, njy, njz);
    if (lane < 17) {
        float4 f = make_float4(f0, f1, f2, f3);
        sf[warp][lane] = f;
        g_feat[i * 17 + lane] = f;
    }
    __syncwarp();

    for (int e = 0; e < 17; e++) {
        float4 f = sf[warp][e];
        float h = ba;
        h = fmaf(f.x, wa0, h); h = fmaf(f.y, wa1, h);
        h = fmaf(f.z, wa2, h); h = fmaf(f.w, wa3, h);
        sh[warp][e][lane] = fmaxf(h, 0.f);
    }
    __syncwarp();

    float best = -CUDART_INF_F;
    for (int e = 0; e < 17; e++) {
        float o0 = bb, o1 = 0.f, o2 = 0.f, o3 = 0.f;
        const float4* hv4 = (const float4*)sh[warp][e];
#pragma unroll
        for (int m = 0; m < 8; m++) {
            float4 hv = hv4[m];
            o0 = fmaf(hv.x, wb[4 * m + 0], o0);
            o1 = fmaf(hv.y, wb[4 * m + 1], o1);
            o2 = fmaf(hv.z, wb[4 * m + 2], o2);
            o3 = fmaf(hv.w, wb[4 * m + 3], o3);
        }
        best = fmaxf(best, (o0 + o1) + (o2 + o3));
    }
    float x1v = fmaxf(best, 0.f);

    sh[warp][0][lane] = x1v;
    __syncwarp();
    float w2[32];
#pragma unroll
    for (int k = 0; k < 32; k++) w2[k] = w2a[k * 32 + lane];
    float a0 = b2a[lane], a1 = 0.f, a2 = 0.f, a3 = 0.f;
    const float4* xv4 = (const float4*)sh[warp][0];
#pragma unroll
    for (int m = 0; m < 8; m++) {
        float4 xv = xv4[m];
        a0 = fmaf(xv.x, w2[4 * m + 0], a0);
        a1 = fmaf(xv.y, w2[4 * m + 1], a1);
        a2 = fmaf(xv.z, w2[4 * m + 2], a2);
        a3 = fmaf(xv.w, w2[4 * m + 3], a3);
    }
    g_y[i * CH + lane] = (a0 + a1) + (a2 + a3);
}

// ---------------------------------------------------------------------------
// conv2 (+ fused global max pool)
// ---------------------------------------------------------------------------
__global__ __launch_bounds__(256) void conv2_kernel(
    const float* __restrict__ w2a,
    const float* __restrict__ w2b, const float* __restrict__ b2b)
{
    __shared__ int   si[8][20];
    __shared__ float sh[8][17][32];
    __shared__ float red[8][32];
    int warp = threadIdx.x >> 5;
    int lane = threadIdx.x & 31;
    int i    = blockIdx.x * 8 + warp;

    float wa32 = w2a[32 * 32 + lane], wa33 = w2a[33 * 32 + lane];
    float wa34 = w2a[34 * 32 + lane], wa35 = w2a[35 * 32 + lane];
    float wb[32];
#pragma unroll
    for (int k = 0; k < 32; k++) wb[k] = w2b[k * 32 + lane];
    float bb = b2b[lane];

    int j = (lane < KNN) ? g_knn[i * KNN + lane] : i;
    if (lane < 17) si[warp][lane] = j;
    __syncwarp();

    float yv[17];
#pragma unroll
    for (int e = 0; e < 17; e++)
        yv[e] = g_y[si[warp][e] * CH + lane];

#pragma unroll
    for (int e = 0; e < 17; e++) {
        float4 f = g_feat[i * 17 + e];
        float h = yv[e];
        h = fmaf(f.x, wa32, h); h = fmaf(f.y, wa33, h);
        h = fmaf(f.z, wa34, h); h = fmaf(f.w, wa35, h);
        sh[warp][e][lane] = fmaxf(h, 0.f);
    }
    __syncwarp();

    float best = -CUDART_INF_F;
    for (int e = 0; e < 17; e++) {
        float o0 = bb, o1 = 0.f, o2 = 0.f, o3 = 0.f;
        const float4* hv4 = (const float4*)sh[warp][e];
#pragma unroll
        for (int m = 0; m < 8; m++) {
            float4 hv = hv4[m];
            o0 = fmaf(hv.x, wb[4 * m + 0], o0);
            o1 = fmaf(hv.y, wb[4 * m + 1], o1);
            o2 = fmaf(hv.z, wb[4 * m + 2], o2);
            o3 = fmaf(hv.w, wb[4 * m + 3], o3);
        }
        best = fmaxf(best, (o0 + o1) + (o2 + o3));
    }
    red[warp][lane] = fmaxf(best, 0.f);
    __syncthreads();

    if (warp == 0) {
        float m = red[0][lane];
#pragma unroll
        for (int r = 1; r < 8; r++) m = fmaxf(m, red[r][lane]);
        int b = (blockIdx.x * 8) >> 12;
        atomicMax((int*)&g_pool[b * CH + lane], __float_as_int(m));
    }
}

__global__ void fc_kernel(const float* __restrict__ wc,
                          const float* __restrict__ bc,
                          float* __restrict__ out) {
    int t = threadIdx.x;
    if (t < NB * NCLS) {
        int b = t / NCLS, o = t % NCLS;
        float acc = bc[o];
#pragma unroll
        for (int c = 0; c < CH; c++)
            acc = fmaf(g_pool[b * CH + c], wc[c * NCLS + o], acc);
        out[t] = acc;
    }
}

extern "C" void kernel_launch(void* const* d_in, const int* in_sizes, int n_in,
                              void* d_out, int out_size) {
    const float* pos = (const float*)d_in[0];
    const float* nrm = (const float*)d_in[1];
    const float* w1a = (const float*)d_in[3];
    const float* b1a = (const float*)d_in[4];
    const float* w1b = (const float*)d_in[5];
    const float* b1b = (const float*)d_in[6];
    const float* w2a = (const float*)d_in[7];
    const float* b2a = (const float*)d_in[8];
    const float* w2b = (const float*)d_in[9];
    const float* b2b = (const float*)d_in[10];
    const float* wc  = (const float*)d_in[11];
    const float* bc  = (const float*)d_in[12];
    float* out = (float*)d_out;

    count_kernel<<<MPTS / 256, 256>>>(pos);    // 1 (also zeroes pool)
    scan_kernel<<<NB, 1024>>>();               // 2 (re-zeroes g_cnt)
    scatter_kernel<<<MPTS / 256, 256>>>(pos);  // 3
    knn_kernel<<<MPTS / 8, 256>>>(pos);        // 4 (ncu sample slot)
    conv1_kernel<<<MPTS / 8, 256>>>(pos, nrm, w1a, b1a, w1b, b1b, w2a, b2a);
    conv2_kernel<<<MPTS / 8, 256>>>(w2a, w2b, b2b);
    fc_kernel<<<1, 320>>>(wc, bc, out);
}

// round 12
// speedup vs baseline: 1.1567x; 1.1567x over previous
#include <cuda_runtime.h>
#include <math_constants.h>

#define NB 8
#define NPTS 4096
#define KNN 16
#define MPTS (NB * NPTS)
#define CH 32
#define NCLS 40

__device__ int    g_knn[MPTS * KNN];
__device__ float  g_y[MPTS * CH];
__device__ float4 g_feat[MPTS * 17];
__device__ float  g_pool[NB * CH];

__device__ __forceinline__ float safe_norm3(float x, float y, float z) {
    float s = x * x + y * y + z * z;
    return s > 0.f ? sqrtf(s) : 0.f;
}

__device__ __forceinline__ float angle3(float ax, float ay, float az,
                                        float bx, float by, float bz) {
    float cx = ay * bz - az * by;
    float cy = az * bx - ax * bz;
    float cz = ax * by - ay * bx;
    float cn = safe_norm3(cx, cy, cz);
    float d  = ax * bx + ay * by + az * bz;
    bool ok = (cn > 0.f) || (d != 0.f);
    return ok ? atan2f(cn, d) : 0.f;
}

__global__ void pool_init_kernel() {
    int t = threadIdx.x;
    if (t < NB * CH) g_pool[t] = 0.f;
}

// ---------------------------------------------------------------------------
// kNN v8: two-pass threshold-primed warp-select (R6 machinery + priming).
// 2 queries/warp. Pass 1: per-lane running min over the candidate stream
// (no warp coordination). tau = 16th smallest of the 32 lane-mins — a proven
// upper bound on the true 16th distance. Pass 2: the proven ballot/insert
// machinery with tp clamped to nextafter(tau), so only ~22 inserts/query.
// ---------------------------------------------------------------------------
__global__ __launch_bounds__(256) void knn_kernel(const float* __restrict__ pos,
                                                  int blockBase) {
    const unsigned FULL = 0xFFFFFFFFu;
    const float INF = CUDART_INF_F;
    int bid  = blockBase + blockIdx.x;
    int lane = threadIdx.x & 31;
    int warp = threadIdx.x >> 5;
    int half = lane >> 4;
    int lh   = lane & 15;
    int hsh  = half << 4;

    int qbase = bid * 16;
    int q0    = qbase + warp * 2;          // even
    int batch = bid >> 8;
    int q0l   = q0 & (NPTS - 1);
    int q1l   = q0l + 1;
    int selfb = q0l & ~31;

    float p0x = pos[3 * q0 + 0], p0y = pos[3 * q0 + 1], p0z = pos[3 * q0 + 2];
    float p1x = pos[3 * q0 + 3], p1y = pos[3 * q0 + 4], p1z = pos[3 * q0 + 5];
    float m2x0 = -2.f * p0x, m2y0 = -2.f * p0y, m2z0 = -2.f * p0z;
    float m2x1 = -2.f * p1x, m2y1 = -2.f * p1y, m2z1 = -2.f * p1z;

    const float* bp = pos + (size_t)batch * NPTS * 3;
    __shared__ float4 tile[8][1024];    // per... no: shared across block
    // NOTE: tile is block-shared (all 8 warps scan the same batch's points)
    float4 (*tl)[1024] = tile;          // silence unused-dim style
    (void)tl;

    // ---------------- pass 1: per-lane running mins ----------------
    float min0 = INF, min1 = INF;
    for (int t = 0; t < NPTS; t += 1024) {
        __syncthreads();
#pragma unroll
        for (int u = 0; u < 4; u++) {
            int p = t + threadIdx.x + u * 256;
            float cx = bp[3 * p + 0], cy = bp[3 * p + 1], cz = bp[3 * p + 2];
            tile[0][threadIdx.x + u * 256] =
                make_float4(cx, cy, cz, cx * cx + cy * cy + cz * cz);
        }
        __syncthreads();
#pragma unroll 4
        for (int s = 0; s < 32; s++) {
            int base = t + s * 32;
            float4 c = tile[0][s * 32 + lane];
            float d0 = fmaf(c.x, m2x0, fmaf(c.y, m2y0, fmaf(c.z, m2z0, c.w)));
            float d1 = fmaf(c.x, m2x1, fmaf(c.y, m2y1, fmaf(c.z, m2z1, c.w)));
            if (base == selfb) {
                int cl = base + lane;
                if (cl == q0l) d0 = INF;
                if (cl == q1l) d1 = INF;
            }
            min0 = fminf(min0, d0);
            min1 = fminf(min1, d1);
        }
    }

    // ---------------- tau: 16th smallest of the 32 lane-mins ----------------
    float L = INF;
#pragma unroll 8
    for (int src = 0; src < 32; src++) {
        float v0 = __shfl_sync(FULL, min0, src);
        float v1 = __shfl_sync(FULL, min1, src);
        float v = half ? v1 : v0;
        unsigned ble = __ballot_sync(FULL, L <= v);
        int pos_ = __popc((ble >> hsh) & 0xFFFFu);
        float Lup = __shfl_up_sync(FULL, L, 1);
        if (lh == pos_)      L = v;
        else if (lh > pos_)  L = Lup;
    }
    float t0e = nextafterf(__shfl_sync(FULL, L, 15), INF);   // tau0+
    float t1e = nextafterf(__shfl_sync(FULL, L, 31), INF);   // tau1+

    // ---------------- pass 2: exact selection under primed threshold --------
    L = INF;
    int LI = batch * NPTS;
    float tp0 = t0e, tp1 = t1e;

    for (int t = 0; t < NPTS; t += 1024) {
        __syncthreads();
#pragma unroll
        for (int u = 0; u < 4; u++) {
            int p = t + threadIdx.x + u * 256;
            float cx = bp[3 * p + 0], cy = bp[3 * p + 1], cz = bp[3 * p + 2];
            tile[0][threadIdx.x + u * 256] =
                make_float4(cx, cy, cz, cx * cx + cy * cy + cz * cz);
        }
        __syncthreads();
#pragma unroll 4
        for (int s = 0; s < 32; s++) {
            int base = t + s * 32;
            float4 c = tile[0][s * 32 + lane];
            float d0 = fmaf(c.x, m2x0, fmaf(c.y, m2y0, fmaf(c.z, m2z0, c.w)));
            float d1 = fmaf(c.x, m2x1, fmaf(c.y, m2y1, fmaf(c.z, m2z1, c.w)));
            if (base == selfb) {
                int cl = base + lane;
                if (cl == q0l) d0 = INF;
                if (cl == q1l) d1 = INF;
            }
            unsigned bal0 = __ballot_sync(FULL, d0 < tp0);
            unsigned bal1 = __ballot_sync(FULL, d1 < tp1);
            while (bal0 | bal1) {
                int s0 = __ffs(bal0) - 1;
                int s1 = __ffs(bal1) - 1;
                float v0 = __shfl_sync(FULL, d0, bal0 ? s0 : 0);
                float v1 = __shfl_sync(FULL, d1, bal1 ? s1 : 0);
                float v;
                int   vi;
                if (half) { v = bal1 ? v1 : INF; vi = base + s1; }
                else      { v = bal0 ? v0 : INF; vi = base + s0; }
                unsigned ble = __ballot_sync(FULL, L <= v);
                int pos_ = __popc((ble >> hsh) & 0xFFFFu);
                float Lup = __shfl_up_sync(FULL, L, 1);
                int  LIup = __shfl_up_sync(FULL, LI, 1);
                if (lh == pos_)      { L = v;   LI = vi;   }
                else if (lh > pos_)  { L = Lup; LI = LIup; }
                tp0 = fminf(t0e, __shfl_sync(FULL, L, 15));
                tp1 = fminf(t1e, __shfl_sync(FULL, L, 31));
                bal0 &= bal0 - 1;
                bal1 &= bal1 - 1;
            }
        }
    }
    int q = q0 + half;
    g_knn[q * KNN + lh] = batch * NPTS + LI;
}

// ---------------------------------------------------------------------------
// conv1 (+ fused y = w2a[0:32]^T x1 + b2a; materializes PPF feats)
// ---------------------------------------------------------------------------
__global__ __launch_bounds__(256) void conv1_kernel(
    const float* __restrict__ pos, const float* __restrict__ nrm,
    const float* __restrict__ w1a, const float* __restrict__ b1a,
    const float* __restrict__ w1b, const float* __restrict__ b1b,
    const float* __restrict__ w2a, const float* __restrict__ b2a)
{
    __shared__ float4 sf[8][20];
    __shared__ float  sh[8][17][32];
    int warp = threadIdx.x >> 5;
    int lane = threadIdx.x & 31;
    int i    = blockIdx.x * 8 + warp;

    float wa0 = w1a[0 * 32 + lane], wa1 = w1a[1 * 32 + lane];
    float wa2 = w1a[2 * 32 + lane], wa3 = w1a[3 * 32 + lane];
    float ba  = b1a[lane];
    float wb[32];
#pragma unroll
    for (int k = 0; k < 32; k++) wb[k] = w1b[k * 32 + lane];
    float bb = b1b[lane];

    float pix = pos[3 * i + 0], piy = pos[3 * i + 1], piz = pos[3 * i + 2];
    float nix = nrm[3 * i + 0], niy = nrm[3 * i + 1], niz = nrm[3 * i + 2];

    int j = (lane < KNN) ? g_knn[i * KNN + lane] : i;   // lane16 = self loop
    float pjx = pos[3 * j + 0], pjy = pos[3 * j + 1], pjz = pos[3 * j + 2];
    float njx = nrm[3 * j + 0], njy = nrm[3 * j + 1], njz = nrm[3 * j + 2];

    float px = pjx - pix, py = pjy - piy, pz = pjz - piz;
    float f0 = safe_norm3(px, py, pz);
    float f1 = angle3(nix, niy, niz, px, py, pz);
    float f2 = angle3(njx, njy, njz, px, py, pz);
    float f3 = angle3(nix, niy, niz, njx, njy, njz);
    if (lane < 17) {
        float4 f = make_float4(f0, f1, f2, f3);
        sf[warp][lane] = f;
        g_feat[i * 17 + lane] = f;
    }
    __syncwarp();

    for (int e = 0; e < 17; e++) {
        float4 f = sf[warp][e];
        float h = ba;
        h = fmaf(f.x, wa0, h); h = fmaf(f.y, wa1, h);
        h = fmaf(f.z, wa2, h); h = fmaf(f.w, wa3, h);
        sh[warp][e][lane] = fmaxf(h, 0.f);
    }
    __syncwarp();

    float best = -CUDART_INF_F;
    for (int e = 0; e < 17; e++) {
        float o0 = bb, o1 = 0.f, o2 = 0.f, o3 = 0.f;
        const float4* hv4 = (const float4*)sh[warp][e];
#pragma unroll
        for (int m = 0; m < 8; m++) {
            float4 hv = hv4[m];
            o0 = fmaf(hv.x, wb[4 * m + 0], o0);
            o1 = fmaf(hv.y, wb[4 * m + 1], o1);
            o2 = fmaf(hv.z, wb[4 * m + 2], o2);
            o3 = fmaf(hv.w, wb[4 * m + 3], o3);
        }
        best = fmaxf(best, (o0 + o1) + (o2 + o3));
    }
    float x1v = fmaxf(best, 0.f);

    sh[warp][0][lane] = x1v;
    __syncwarp();
    float w2[32];
#pragma unroll
    for (int k = 0; k < 32; k++) w2[k] = w2a[k * 32 + lane];
    float a0 = b2a[lane], a1 = 0.f, a2 = 0.f, a3 = 0.f;
    const float4* xv4 = (const float4*)sh[warp][0];
#pragma unroll
    for (int m = 0; m < 8; m++) {
        float4 xv = xv4[m];
        a0 = fmaf(xv.x, w2[4 * m + 0], a0);
        a1 = fmaf(xv.y, w2[4 * m + 1], a1);
        a2 = fmaf(xv.z, w2[4 * m + 2], a2);
        a3 = fmaf(xv.w, w2[4 * m + 3], a3);
    }
    g_y[i * CH + lane] = (a0 + a1) + (a2 + a3);
}

// ---------------------------------------------------------------------------
// conv2 (+ fused global max pool)
// ---------------------------------------------------------------------------
__global__ __launch_bounds__(256) void conv2_kernel(
    const float* __restrict__ w2a,
    const float* __restrict__ w2b, const float* __restrict__ b2b)
{
    __shared__ int   si[8][20];
    __shared__ float sh[8][17][32];
    __shared__ float red[8][32];
    int warp = threadIdx.x >> 5;
    int lane = threadIdx.x & 31;
    int i    = blockIdx.x * 8 + warp;

    float wa32 = w2a[32 * 32 + lane], wa33 = w2a[33 * 32 + lane];
    float wa34 = w2a[34 * 32 + lane], wa35 = w2a[35 * 32 + lane];
    float wb[32];
#pragma unroll
    for (int k = 0; k < 32; k++) wb[k] = w2b[k * 32 + lane];
    float bb = b2b[lane];

    int j = (lane < KNN) ? g_knn[i * KNN + lane] : i;
    if (lane < 17) si[warp][lane] = j;
    __syncwarp();

    float yv[17];
#pragma unroll
    for (int e = 0; e < 17; e++)
        yv[e] = g_y[si[warp][e] * CH + lane];

#pragma unroll
    for (int e = 0; e < 17; e++) {
        float4 f = g_feat[i * 17 + e];
        float h = yv[e];
        h = fmaf(f.x, wa32, h); h = fmaf(f.y, wa33, h);
        h = fmaf(f.z, wa34, h); h = fmaf(f.w, wa35, h);
        sh[warp][e][lane] = fmaxf(h, 0.f);
    }
    __syncwarp();

    float best = -CUDART_INF_F;
    for (int e = 0; e < 17; e++) {
        float o0 = bb, o1 = 0.f, o2 = 0.f, o3 = 0.f;
        const float4* hv4 = (const float4*)sh[warp][e];
#pragma unroll
        for (int m = 0; m < 8; m++) {
            float4 hv = hv4[m];
            o0 = fmaf(hv.x, wb[4 * m + 0], o0);
            o1 = fmaf(hv.y, wb[4 * m + 1], o1);
            o2 = fmaf(hv.z, wb[4 * m + 2], o2);
            o3 = fmaf(hv.w, wb[4 * m + 3], o3);
        }
        best = fmaxf(best, (o0 + o1) + (o2 + o3));
    }
    red[warp][lane] = fmaxf(best, 0.f);
    __syncthreads();

    if (warp == 0) {
        float m = red[0][lane];
#pragma unroll
        for (int r = 1; r < 8; r++) m = fmaxf(m, red[r][lane]);
        int b = (blockIdx.x * 8) >> 12;
        atomicMax((int*)&g_pool[b * CH + lane], __float_as_int(m));
    }
}

__global__ void fc_kernel(const float* __restrict__ wc,
                          const float* __restrict__ bc,
                          float* __restrict__ out) {
    int t = threadIdx.x;
    if (t < NB * NCLS) {
        int b = t / NCLS, o = t % NCLS;
        float acc = bc[o];
#pragma unroll
        for (int c = 0; c < CH; c++)
            acc = fmaf(g_pool[b * CH + c], wc[c * NCLS + o], acc);
        out[t] = acc;
    }
}

extern "C" void kernel_launch(void* const* d_in, const int* in_sizes, int n_in,
                              void* d_out, int out_size) {
    const float* pos = (const float*)d_in[0];
    const float* nrm = (const float*)d_in[1];
    const float* w1a = (const float*)d_in[3];
    const float* b1a = (const float*)d_in[4];
    const float* w1b = (const float*)d_in[5];
    const float* b1b = (const float*)d_in[6];
    const float* w2a = (const float*)d_in[7];
    const float* b2a = (const float*)d_in[8];
    const float* w2b = (const float*)d_in[9];
    const float* b2b = (const float*)d_in[10];
    const float* wc  = (const float*)d_in[11];
    const float* bc  = (const float*)d_in[12];
    float* out = (float*)d_out;

    knn_kernel<<<1024, 256>>>(pos, 0);         // 1
    knn_kernel<<<1024, 256>>>(pos, 1024);      // 2
    pool_init_kernel<<<1, 256>>>();            // 3
    conv1_kernel<<<MPTS / 8, 256>>>(pos, nrm, w1a, b1a, w1b, b1b, w2a, b2a); // 4 (ncu)
    conv2_kernel<<<MPTS / 8, 256>>>(w2a, w2b, b2b);
    fc_kernel<<<1, 320>>>(wc, bc, out);
}

// round 13
// speedup vs baseline: 1.7726x; 1.5325x over previous
#include <cuda_runtime.h>
#include <math_constants.h>

#define NB 8
#define NPTS 4096
#define KNN 16
#define MPTS (NB * NPTS)
#define CH 32
#define NCLS 40

__device__ int    g_knn[MPTS * KNN];
__device__ float  g_y[MPTS * CH];
__device__ float4 g_feat[MPTS * 17];
__device__ float  g_pool[NB * CH];

__device__ __forceinline__ float safe_norm3(float x, float y, float z) {
    float s = x * x + y * y + z * z;
    return s > 0.f ? sqrtf(s) : 0.f;
}

__device__ __forceinline__ float angle3(float ax, float ay, float az,
                                        float bx, float by, float bz) {
    float cx = ay * bz - az * by;
    float cy = az * bx - ax * bz;
    float cz = ax * by - ay * bx;
    float cn = safe_norm3(cx, cy, cz);
    float d  = ax * bx + ay * by + az * bz;
    bool ok = (cn > 0.f) || (d != 0.f);
    return ok ? atan2f(cn, d) : 0.f;
}

__global__ void pool_init_kernel() {
    int t = threadIdx.x;
    if (t < NB * CH) g_pool[t] = 0.f;
}

// ---------------------------------------------------------------------------
// kNN v8b: two-pass threshold-primed warp-select (16KB tile this time).
// 2 queries/warp. Pass 1: per-lane running min over the candidate stream.
// tau = 16th smallest of the 32 lane-mins (upper bound on true 16th dist).
// Pass 2: proven ballot/insert machinery with tp primed to nextafter(tau)
// => ~22 inserts/query instead of ~79.
// ---------------------------------------------------------------------------
__global__ __launch_bounds__(256) void knn_kernel(const float* __restrict__ pos) {
    const unsigned FULL = 0xFFFFFFFFu;
    const float INF = CUDART_INF_F;
    int lane = threadIdx.x & 31;
    int warp = threadIdx.x >> 5;
    int half = lane >> 4;
    int lh   = lane & 15;
    int hsh  = half << 4;

    int qbase = blockIdx.x * 16;
    int q0    = qbase + warp * 2;          // even
    int batch = blockIdx.x >> 8;
    int q0l   = q0 & (NPTS - 1);
    int q1l   = q0l + 1;
    int selfb = q0l & ~31;

    float p0x = pos[3 * q0 + 0], p0y = pos[3 * q0 + 1], p0z = pos[3 * q0 + 2];
    float p1x = pos[3 * q0 + 3], p1y = pos[3 * q0 + 4], p1z = pos[3 * q0 + 5];
    float m2x0 = -2.f * p0x, m2y0 = -2.f * p0y, m2z0 = -2.f * p0z;
    float m2x1 = -2.f * p1x, m2y1 = -2.f * p1y, m2z1 = -2.f * p1z;

    const float* bp = pos + (size_t)batch * NPTS * 3;
    __shared__ float4 tile[1024];          // 16 KB — occupancy-friendly

    // ---------------- pass 1: per-lane running mins ----------------
    float min0 = INF, min1 = INF;
    for (int t = 0; t < NPTS; t += 1024) {
        __syncthreads();
#pragma unroll
        for (int u = 0; u < 4; u++) {
            int p = t + threadIdx.x + u * 256;
            float cx = bp[3 * p + 0], cy = bp[3 * p + 1], cz = bp[3 * p + 2];
            tile[threadIdx.x + u * 256] =
                make_float4(cx, cy, cz, cx * cx + cy * cy + cz * cz);
        }
        __syncthreads();
#pragma unroll 4
        for (int s = 0; s < 32; s++) {
            int base = t + s * 32;
            float4 c = tile[s * 32 + lane];
            float d0 = fmaf(c.x, m2x0, fmaf(c.y, m2y0, fmaf(c.z, m2z0, c.w)));
            float d1 = fmaf(c.x, m2x1, fmaf(c.y, m2y1, fmaf(c.z, m2z1, c.w)));
            if (base == selfb) {
                int cl = base + lane;
                if (cl == q0l) d0 = INF;
                if (cl == q1l) d1 = INF;
            }
            min0 = fminf(min0, d0);
            min1 = fminf(min1, d1);
        }
    }

    // ---------------- tau: 16th smallest of the 32 lane-mins ----------------
    float L = INF;
#pragma unroll 8
    for (int src = 0; src < 32; src++) {
        float v0 = __shfl_sync(FULL, min0, src);
        float v1 = __shfl_sync(FULL, min1, src);
        float v = half ? v1 : v0;
        unsigned ble = __ballot_sync(FULL, L <= v);
        int pos_ = __popc((ble >> hsh) & 0xFFFFu);
        float Lup = __shfl_up_sync(FULL, L, 1);
        if (lh == pos_)      L = v;
        else if (lh > pos_)  L = Lup;
    }
    float t0e = nextafterf(__shfl_sync(FULL, L, 15), INF);   // tau0+
    float t1e = nextafterf(__shfl_sync(FULL, L, 31), INF);   // tau1+

    // ---------------- pass 2: exact selection under primed threshold --------
    L = INF;
    int LI = batch * NPTS;
    float tp0 = t0e, tp1 = t1e;

    for (int t = 0; t < NPTS; t += 1024) {
        __syncthreads();
#pragma unroll
        for (int u = 0; u < 4; u++) {
            int p = t + threadIdx.x + u * 256;
            float cx = bp[3 * p + 0], cy = bp[3 * p + 1], cz = bp[3 * p + 2];
            tile[threadIdx.x + u * 256] =
                make_float4(cx, cy, cz, cx * cx + cy * cy + cz * cz);
        }
        __syncthreads();
#pragma unroll 4
        for (int s = 0; s < 32; s++) {
            int base = t + s * 32;
            float4 c = tile[s * 32 + lane];
            float d0 = fmaf(c.x, m2x0, fmaf(c.y, m2y0, fmaf(c.z, m2z0, c.w)));
            float d1 = fmaf(c.x, m2x1, fmaf(c.y, m2y1, fmaf(c.z, m2z1, c.w)));
            if (base == selfb) {
                int cl = base + lane;
                if (cl == q0l) d0 = INF;
                if (cl == q1l) d1 = INF;
            }
            unsigned bal0 = __ballot_sync(FULL, d0 < tp0);
            unsigned bal1 = __ballot_sync(FULL, d1 < tp1);
            while (bal0 | bal1) {
                int s0 = __ffs(bal0) - 1;
                int s1 = __ffs(bal1) - 1;
                float v0 = __shfl_sync(FULL, d0, bal0 ? s0 : 0);
                float v1 = __shfl_sync(FULL, d1, bal1 ? s1 : 0);
                float v;
                int   vi;
                if (half) { v = bal1 ? v1 : INF; vi = base + s1; }
                else      { v = bal0 ? v0 : INF; vi = base + s0; }
                unsigned ble = __ballot_sync(FULL, L <= v);
                int pos_ = __popc((ble >> hsh) & 0xFFFFu);
                float Lup = __shfl_up_sync(FULL, L, 1);
                int  LIup = __shfl_up_sync(FULL, LI, 1);
                if (lh == pos_)      { L = v;   LI = vi;   }
                else if (lh > pos_)  { L = Lup; LI = LIup; }
                tp0 = fminf(t0e, __shfl_sync(FULL, L, 15));
                tp1 = fminf(t1e, __shfl_sync(FULL, L, 31));
                bal0 &= bal0 - 1;
                bal1 &= bal1 - 1;
            }
        }
    }
    int q = q0 + half;
    g_knn[q * KNN + lh] = batch * NPTS + LI;
}

// ---------------------------------------------------------------------------
// conv1 (+ fused y = w2a[0:32]^T x1 + b2a; materializes PPF feats)
// ---------------------------------------------------------------------------
__global__ __launch_bounds__(256) void conv1_kernel(
    const float* __restrict__ pos, const float* __restrict__ nrm,
    const float* __restrict__ w1a, const float* __restrict__ b1a,
    const float* __restrict__ w1b, const float* __restrict__ b1b,
    const float* __restrict__ w2a, const float* __restrict__ b2a)
{
    __shared__ float4 sf[8][20];
    __shared__ float  sh[8][17][32];
    int warp = threadIdx.x >> 5;
    int lane = threadIdx.x & 31;
    int i    = blockIdx.x * 8 + warp;

    float wa0 = w1a[0 * 32 + lane], wa1 = w1a[1 * 32 + lane];
    float wa2 = w1a[2 * 32 + lane], wa3 = w1a[3 * 32 + lane];
    float ba  = b1a[lane];
    float wb[32];
#pragma unroll
    for (int k = 0; k < 32; k++) wb[k] = w1b[k * 32 + lane];
    float bb = b1b[lane];

    float pix = pos[3 * i + 0], piy = pos[3 * i + 1], piz = pos[3 * i + 2];
    float nix = nrm[3 * i + 0], niy = nrm[3 * i + 1], niz = nrm[3 * i + 2];

    int j = (lane < KNN) ? g_knn[i * KNN + lane] : i;   // lane16 = self loop
    float pjx = pos[3 * j + 0], pjy = pos[3 * j + 1], pjz = pos[3 * j + 2];
    float njx = nrm[3 * j + 0], njy = nrm[3 * j + 1], njz = nrm[3 * j + 2];

    float px = pjx - pix, py = pjy - piy, pz = pjz - piz;
    float f0 = safe_norm3(px, py, pz);
    float f1 = angle3(nix, niy, niz, px, py, pz);
    float f2 = angle3(njx, njy, njz, px, py, pz);
    float f3 = angle3(nix, niy, niz, njx, njy, njz);
    if (lane < 17) {
        float4 f = make_float4(f0, f1, f2, f3);
        sf[warp][lane] = f;
        g_feat[i * 17 + lane] = f;
    }
    __syncwarp();

    for (int e = 0; e < 17; e++) {
        float4 f = sf[warp][e];
        float h = ba;
        h = fmaf(f.x, wa0, h); h = fmaf(f.y, wa1, h);
        h = fmaf(f.z, wa2, h); h = fmaf(f.w, wa3, h);
        sh[warp][e][lane] = fmaxf(h, 0.f);
    }
    __syncwarp();

    float best = -CUDART_INF_F;
    for (int e = 0; e < 17; e++) {
        float o0 = bb, o1 = 0.f, o2 = 0.f, o3 = 0.f;
        const float4* hv4 = (const float4*)sh[warp][e];
#pragma unroll
        for (int m = 0; m < 8; m++) {
            float4 hv = hv4[m];
            o0 = fmaf(hv.x, wb[4 * m + 0], o0);
            o1 = fmaf(hv.y, wb[4 * m + 1], o1);
            o2 = fmaf(hv.z, wb[4 * m + 2], o2);
            o3 = fmaf(hv.w, wb[4 * m + 3], o3);
        }
        best = fmaxf(best, (o0 + o1) + (o2 + o3));
    }
    float x1v = fmaxf(best, 0.f);

    sh[warp][0][lane] = x1v;
    __syncwarp();
    float w2[32];
#pragma unroll
    for (int k = 0; k < 32; k++) w2[k] = w2a[k * 32 + lane];
    float a0 = b2a[lane], a1 = 0.f, a2 = 0.f, a3 = 0.f;
    const float4* xv4 = (const float4*)sh[warp][0];
#pragma unroll
    for (int m = 0; m < 8; m++) {
        float4 xv = xv4[m];
        a0 = fmaf(xv.x, w2[4 * m + 0], a0);
        a1 = fmaf(xv.y, w2[4 * m + 1], a1);
        a2 = fmaf(xv.z, w2[4 * m + 2], a2);
        a3 = fmaf(xv.w, w2[4 * m + 3], a3);
    }
    g_y[i * CH + lane] = (a0 + a1) + (a2 + a3);
}

// ---------------------------------------------------------------------------
// conv2 (+ fused global max pool)
// ---------------------------------------------------------------------------
__global__ __launch_bounds__(256) void conv2_kernel(
    const float* __restrict__ w2a,
    const float* __restrict__ w2b, const float* __restrict__ b2b)
{
    __shared__ int   si[8][20];
    __shared__ float sh[8][17][32];
    __shared__ float red[8][32];
    int warp = threadIdx.x >> 5;
    int lane = threadIdx.x & 31;
    int i    = blockIdx.x * 8 + warp;

    float wa32 = w2a[32 * 32 + lane], wa33 = w2a[33 * 32 + lane];
    float wa34 = w2a[34 * 32 + lane], wa35 = w2a[35 * 32 + lane];
    float wb[32];
#pragma unroll
    for (int k = 0; k < 32; k++) wb[k] = w2b[k * 32 + lane];
    float bb = b2b[lane];

    int j = (lane < KNN) ? g_knn[i * KNN + lane] : i;
    if (lane < 17) si[warp][lane] = j;
    __syncwarp();

    float yv[17];
#pragma unroll
    for (int e = 0; e < 17; e++)
        yv[e] = g_y[si[warp][e] * CH + lane];

#pragma unroll
    for (int e = 0; e < 17; e++) {
        float4 f = g_feat[i * 17 + e];
        float h = yv[e];
        h = fmaf(f.x, wa32, h); h = fmaf(f.y, wa33, h);
        h = fmaf(f.z, wa34, h); h = fmaf(f.w, wa35, h);
        sh[warp][e][lane] = fmaxf(h, 0.f);
    }
    __syncwarp();

    float best = -CUDART_INF_F;
    for (int e = 0; e < 17; e++) {
        float o0 = bb, o1 = 0.f, o2 = 0.f, o3 = 0.f;
        const float4* hv4 = (const float4*)sh[warp][e];
#pragma unroll
        for (int m = 0; m < 8; m++) {
            float4 hv = hv4[m];
            o0 = fmaf(hv.x, wb[4 * m + 0], o0);
            o1 = fmaf(hv.y, wb[4 * m + 1], o1);
            o2 = fmaf(hv.z, wb[4 * m + 2], o2);
            o3 = fmaf(hv.w, wb[4 * m + 3], o3);
        }
        best = fmaxf(best, (o0 + o1) + (o2 + o3));
    }
    red[warp][lane] = fmaxf(best, 0.f);
    __syncthreads();

    if (warp == 0) {
        float m = red[0][lane];
#pragma unroll
        for (int r = 1; r < 8; r++) m = fmaxf(m, red[r][lane]);
        int b = (blockIdx.x * 8) >> 12;
        atomicMax((int*)&g_pool[b * CH + lane], __float_as_int(m));
    }
}

__global__ void fc_kernel(const float* __restrict__ wc,
                          const float* __restrict__ bc,
                          float* __restrict__ out) {
    int t = threadIdx.x;
    if (t < NB * NCLS) {
        int b = t / NCLS, o = t % NCLS;
        float acc = bc[o];
#pragma unroll
        for (int c = 0; c < CH; c++)
            acc = fmaf(g_pool[b * CH + c], wc[c * NCLS + o], acc);
        out[t] = acc;
    }
}

extern "C" void kernel_launch(void* const* d_in, const int* in_sizes, int n_in,
                              void* d_out, int out_size) {
    const float* pos = (const float*)d_in[0];
    const float* nrm = (const float*)d_in[1];
    const float* w1a = (const float*)d_in[3];
    const float* b1a = (const float*)d_in[4];
    const float* w1b = (const float*)d_in[5];
    const float* b1b = (const float*)d_in[6];
    const float* w2a = (const float*)d_in[7];
    const float* b2a = (const float*)d_in[8];
    const float* w2b = (const float*)d_in[9];
    const float* b2b = (const float*)d_in[10];
    const float* wc  = (const float*)d_in[11];
    const float* bc  = (const float*)d_in[12];
    float* out = (float*)d_out;

    pool_init_kernel<<<1, 256>>>();            // 1
    knn_kernel<<<MPTS / 16, 256>>>(pos);       // 2
    conv1_kernel<<<MPTS / 8, 256>>>(pos, nrm, w1a, b1a, w1b, b1b, w2a, b2a); // 3
    conv2_kernel<<<MPTS / 8, 256>>>(w2a, w2b, b2b);   // 4 (ncu sample slot)
    fc_kernel<<<1, 320>>>(wc, bc, out);        // 5
}